// round 1
// baseline (speedup 1.0000x reference)
#include <cuda_runtime.h>
#include <cuda_bf16.h>
#include <math.h>
#include <stddef.h>

#define N_NODES 50000
#define N_EDGES 800000
#define IN_FEATS 256
#define HD 256          // NUM_HEADS * OUT_FEATS
#define NUM_HEADS 8
#define OUT_FEATS 32
#define NUM_ET 5

// ---------------- scratch (static device globals; no allocation) ----------
__device__ float g_feat_src[(size_t)N_NODES * HD];       // 51.2 MB
__device__ int   g_cnt[(size_t)N_NODES * NUM_ET];        // 1 MB
__device__ float g_w[(size_t)N_NODES * NUM_ET * NUM_HEADS]; // 8 MB

// ---------------- vectorized global reduction -----------------------------
__device__ __forceinline__ void red_add_v4(float* addr, float4 v) {
    asm volatile("red.global.add.v4.f32 [%0], {%1,%2,%3,%4};"
                 :: "l"(addr), "f"(v.x), "f"(v.y), "f"(v.z), "f"(v.w)
                 : "memory");
}

// ---------------- 1) GEMM: C[M,256] = A[M,256] * B[256,256]^T -------------
// Tiles: 64(m) x 64(n) x 32(k), 256 threads, 4x4 per thread.
__global__ void gemm_kernel(const float* __restrict__ A,
                            const float* __restrict__ B,
                            float* __restrict__ C, int M) {
    __shared__ float As[64][36];   // m-major, padded (row = 144B, 16B aligned)
    __shared__ float Bs[32][68];   // k-major, padded (row = 272B, 16B aligned)

    const int tid = threadIdx.x;
    const int tx = tid & 15;        // n direction
    const int ty = tid >> 4;        // m direction
    const int m0 = blockIdx.x * 64;
    const int n0 = blockIdx.y * 64;

    float acc[4][4];
#pragma unroll
    for (int i = 0; i < 4; i++)
#pragma unroll
        for (int j = 0; j < 4; j++) acc[i][j] = 0.f;

    for (int k0 = 0; k0 < 256; k0 += 32) {
#pragma unroll
        for (int r = 0; r < 2; r++) {
            int idx = tid + r * 256;       // float4 slot 0..511
            int row = idx >> 3;            // 0..63
            int c4  = idx & 7;             // 0..7
            // A tile (guarded on M)
            float4 va = make_float4(0.f, 0.f, 0.f, 0.f);
            if (m0 + row < M)
                va = *(const float4*)(A + (size_t)(m0 + row) * 256 + k0 + c4 * 4);
            *(float4*)&As[row][c4 * 4] = va;
            // B tile (N=256, always in range), store k-major
            float4 vb = *(const float4*)(B + (size_t)(n0 + row) * 256 + k0 + c4 * 4);
            Bs[c4 * 4 + 0][row] = vb.x;
            Bs[c4 * 4 + 1][row] = vb.y;
            Bs[c4 * 4 + 2][row] = vb.z;
            Bs[c4 * 4 + 3][row] = vb.w;
        }
        __syncthreads();

#pragma unroll
        for (int kk = 0; kk < 32; kk++) {
            float a0 = As[ty * 4 + 0][kk];
            float a1 = As[ty * 4 + 1][kk];
            float a2 = As[ty * 4 + 2][kk];
            float a3 = As[ty * 4 + 3][kk];
            float4 b4 = *(const float4*)&Bs[kk][tx * 4];
            acc[0][0] += a0 * b4.x; acc[0][1] += a0 * b4.y; acc[0][2] += a0 * b4.z; acc[0][3] += a0 * b4.w;
            acc[1][0] += a1 * b4.x; acc[1][1] += a1 * b4.y; acc[1][2] += a1 * b4.z; acc[1][3] += a1 * b4.w;
            acc[2][0] += a2 * b4.x; acc[2][1] += a2 * b4.y; acc[2][2] += a2 * b4.z; acc[2][3] += a2 * b4.w;
            acc[3][0] += a3 * b4.x; acc[3][1] += a3 * b4.y; acc[3][2] += a3 * b4.z; acc[3][3] += a3 * b4.w;
        }
        __syncthreads();
    }

#pragma unroll
    for (int i = 0; i < 4; i++) {
        int m = m0 + ty * 4 + i;
        if (m < M) {
            float4 v = make_float4(acc[i][0], acc[i][1], acc[i][2], acc[i][3]);
            *(float4*)(C + (size_t)m * 256 + n0 + tx * 4) = v;
        }
    }
}

// ---------------- 2) per-(dst,type) incoming-edge histogram ---------------
__global__ void count_kernel(const int* __restrict__ dst,
                             const int* __restrict__ ef) {
    int i = blockIdx.x * blockDim.x + threadIdx.x;
    if (i < N_EDGES) {
        atomicAdd(&g_cnt[(size_t)dst[i] * NUM_ET + ef[i]], 1);
    }
}

// ---------------- 3) per-node softmax table w[n,t,h] ----------------------
__global__ void node_softmax_kernel(const float* __restrict__ emb) {
    int idx = blockIdx.x * blockDim.x + threadIdx.x;
    if (idx >= N_NODES * NUM_HEADS) return;
    int n = idx >> 3;
    int h = idx & 7;

    int c[NUM_ET];
    float ev[NUM_ET];
#pragma unroll
    for (int t = 0; t < NUM_ET; t++) {
        c[t] = g_cnt[(size_t)n * NUM_ET + t];
        ev[t] = emb[t * NUM_HEADS + h];
    }
    float m = -INFINITY;
#pragma unroll
    for (int t = 0; t < NUM_ET; t++)
        if (c[t] > 0) m = fmaxf(m, ev[t]);

    float ex[NUM_ET];
    float denom = 0.f;
#pragma unroll
    for (int t = 0; t < NUM_ET; t++) {
        ex[t] = expf(ev[t] - m);
        denom += (float)c[t] * ex[t];
    }
    float inv = 1.f / denom;   // denom==0 only for isolated nodes -> w unread
#pragma unroll
    for (int t = 0; t < NUM_ET; t++)
        g_w[((size_t)n * NUM_ET + t) * NUM_HEADS + h] = ex[t] * inv;
}

// ---------------- 4) edge aggregation + attn output (1 warp / edge) -------
__global__ void agg_kernel(const int* __restrict__ src,
                           const int* __restrict__ dst,
                           const int* __restrict__ ef,
                           float* __restrict__ rst,
                           float* __restrict__ attn_out) {
    int warp = (blockIdx.x * blockDim.x + threadIdx.x) >> 5;
    int lane = threadIdx.x & 31;
    if (warp >= N_EDGES) return;

    int s = __ldg(src + warp);
    int d = __ldg(dst + warp);
    int t = __ldg(ef + warp);

    const float* wrow = g_w + ((size_t)d * NUM_ET + t) * NUM_HEADS;
    const float4* frow = (const float4*)(g_feat_src + (size_t)s * HD);
    float* orow = rst + (size_t)d * HD;

    // attention weights for the two float4 chunks this lane handles:
    // chunk i covers head h = i/8 (32 floats per head = 8 float4s)
    float a0 = __ldg(wrow + (lane >> 3));
    float a1 = __ldg(wrow + (lane >> 3) + 4);

    float4 v0 = __ldg(frow + lane);
    float4 v1 = __ldg(frow + lane + 32);
    v0.x *= a0; v0.y *= a0; v0.z *= a0; v0.w *= a0;
    v1.x *= a1; v1.y *= a1; v1.z *= a1; v1.w *= a1;

    red_add_v4(orow + (size_t)lane * 4, v0);
    red_add_v4(orow + ((size_t)lane + 32) * 4, v1);

    if (lane < NUM_HEADS)
        attn_out[(size_t)warp * NUM_HEADS + lane] = __ldg(wrow + lane);
}

// ---------------- launch ---------------------------------------------------
extern "C" void kernel_launch(void* const* d_in, const int* in_sizes, int n_in,
                              void* d_out, int out_size) {
    const float* feat   = (const float*)d_in[0];   // [N, 256]
    const float* fc_w   = (const float*)d_in[1];   // [256, 256]
    const float* emb    = (const float*)d_in[2];   // [5, 8]
    const int*   e_feat = (const int*)d_in[3];     // [E]
    const int*   src    = (const int*)d_in[4];     // [E]
    const int*   dst    = (const int*)d_in[5];     // [E]

    float* out_rst  = (float*)d_out;                           // [N, 8, 32]
    float* out_attn = (float*)d_out + (size_t)N_NODES * HD;    // [E, 8]

    void* cnt_ptr = nullptr;
    void* fs_ptr  = nullptr;
    cudaGetSymbolAddress(&cnt_ptr, g_cnt);
    cudaGetSymbolAddress(&fs_ptr, g_feat_src);

    // zero histogram + rst accumulation region
    cudaMemsetAsync(cnt_ptr, 0, (size_t)N_NODES * NUM_ET * sizeof(int));
    cudaMemsetAsync(out_rst, 0, (size_t)N_NODES * HD * sizeof(float));

    // 1) GEMM
    {
        dim3 grid((N_NODES + 63) / 64, HD / 64);
        gemm_kernel<<<grid, 256>>>(feat, fc_w, (float*)fs_ptr, N_NODES);
    }
    // 2) histogram
    count_kernel<<<(N_EDGES + 255) / 256, 256>>>(dst, e_feat);
    // 3) per-node softmax table
    node_softmax_kernel<<<(N_NODES * NUM_HEADS + 255) / 256, 256>>>(emb);
    // 4) aggregation + attn output
    {
        int warps = N_EDGES;
        int blocks = (warps * 32 + 255) / 256;
        agg_kernel<<<blocks, 256>>>(src, dst, e_feat, out_rst, out_attn);
    }
}

// round 2
// speedup vs baseline: 1.9313x; 1.9313x over previous
#include <cuda_runtime.h>
#include <cuda_bf16.h>
#include <math.h>
#include <stddef.h>
#include <stdint.h>

#define N_NODES 50000
#define N_EDGES 800000
#define IN_FEATS 256
#define HD 256          // NUM_HEADS * OUT_FEATS
#define NUM_HEADS 8
#define OUT_FEATS 32
#define NUM_ET 5

// ---------------- scratch (static device globals; no allocation) ----------
__device__ float g_feat_src[(size_t)N_NODES * HD];          // 51.2 MB
__device__ int   g_cnt[(size_t)N_NODES * NUM_ET];           // 1 MB
__device__ float g_w[(size_t)N_NODES * NUM_ET * NUM_HEADS]; // 8 MB
__device__ int   g_off[N_NODES];
__device__ int   g_deg[N_NODES];
__device__ int   g_cur[N_NODES];
__device__ int   g_csr[N_EDGES];
__device__ int   g_total;

// =====================================================================
// 1) GEMM: C[M,256] = A[M,256] * B[256,256]^T  via split-bf16 tensor MMA
//    a = hi + lo (bf16 each);  a*b ~= hi_a*hi_b + hi_a*lo_b + lo_a*hi_b
//    BM=128, BN=64, BK=32, 256 threads, 8 warps (4M x 2N), warp 32x32
// =====================================================================
__device__ __forceinline__ void mma_bf16(float* c, const uint32_t* a, const uint32_t* b) {
    asm volatile(
        "mma.sync.aligned.m16n8k16.row.col.f32.bf16.bf16.f32 "
        "{%0,%1,%2,%3},{%4,%5,%6,%7},{%8,%9},{%0,%1,%2,%3};\n"
        : "+f"(c[0]), "+f"(c[1]), "+f"(c[2]), "+f"(c[3])
        : "r"(a[0]), "r"(a[1]), "r"(a[2]), "r"(a[3]), "r"(b[0]), "r"(b[1]));
}

__device__ __forceinline__ void split_store(__nv_bfloat16* ph, __nv_bfloat16* pl, float4 v) {
    __nv_bfloat162 h01, h23, l01, l23;
    h01.x = __float2bfloat16(v.x);
    h01.y = __float2bfloat16(v.y);
    h23.x = __float2bfloat16(v.z);
    h23.y = __float2bfloat16(v.w);
    l01.x = __float2bfloat16(v.x - __bfloat162float(h01.x));
    l01.y = __float2bfloat16(v.y - __bfloat162float(h01.y));
    l23.x = __float2bfloat16(v.z - __bfloat162float(h23.x));
    l23.y = __float2bfloat16(v.w - __bfloat162float(h23.y));
    *(__nv_bfloat162*)(ph)     = h01;
    *(__nv_bfloat162*)(ph + 2) = h23;
    *(__nv_bfloat162*)(pl)     = l01;
    *(__nv_bfloat162*)(pl + 2) = l23;
}

__global__ __launch_bounds__(256) void gemm_bf16x3_kernel(
    const float* __restrict__ A, const float* __restrict__ B,
    float* __restrict__ C, int M) {
    // 40-element row pad (80B = 20 banks): conflict-free fragment loads
    __shared__ __nv_bfloat16 As_h[128][40], As_l[128][40];
    __shared__ __nv_bfloat16 Bs_h[64][40],  Bs_l[64][40];

    const int tid = threadIdx.x;
    const int m0 = blockIdx.x * 128;
    const int n0 = blockIdx.y * 64;
    const int warp = tid >> 5, lane = tid & 31;
    const int wm0 = (warp >> 1) * 32, wn0 = (warp & 1) * 32;
    const int g = lane >> 2, tg = lane & 3;

    float acc[2][4][4];
#pragma unroll
    for (int i = 0; i < 2; i++)
#pragma unroll
        for (int j = 0; j < 4; j++)
#pragma unroll
            for (int q = 0; q < 4; q++) acc[i][j][q] = 0.f;

    for (int k0 = 0; k0 < 256; k0 += 32) {
        // load + split A tile (128x32) : 4 float4 per thread
#pragma unroll
        for (int r = 0; r < 4; r++) {
            int idx = tid + r * 256;
            int row = idx >> 3, c4 = (idx & 7) * 4;
            float4 v = make_float4(0.f, 0.f, 0.f, 0.f);
            if (m0 + row < M)
                v = __ldg((const float4*)(A + (size_t)(m0 + row) * 256 + k0 + c4));
            split_store(&As_h[row][c4], &As_l[row][c4], v);
        }
        // load + split B tile (64x32) : 2 float4 per thread
#pragma unroll
        for (int r = 0; r < 2; r++) {
            int idx = tid + r * 256;
            int row = idx >> 3, c4 = (idx & 7) * 4;
            float4 v = __ldg((const float4*)(B + (size_t)(n0 + row) * 256 + k0 + c4));
            split_store(&Bs_h[row][c4], &Bs_l[row][c4], v);
        }
        __syncthreads();

#pragma unroll
        for (int kf = 0; kf < 2; kf++) {
            const int kA = kf * 16 + tg * 2;
            uint32_t ah[2][4], al[2][4], bh[4][2], bl[4][2];
#pragma unroll
            for (int i = 0; i < 2; i++) {
                int r0 = wm0 + i * 16 + g;
                ah[i][0] = *(const uint32_t*)&As_h[r0][kA];
                ah[i][1] = *(const uint32_t*)&As_h[r0 + 8][kA];
                ah[i][2] = *(const uint32_t*)&As_h[r0][kA + 8];
                ah[i][3] = *(const uint32_t*)&As_h[r0 + 8][kA + 8];
                al[i][0] = *(const uint32_t*)&As_l[r0][kA];
                al[i][1] = *(const uint32_t*)&As_l[r0 + 8][kA];
                al[i][2] = *(const uint32_t*)&As_l[r0][kA + 8];
                al[i][3] = *(const uint32_t*)&As_l[r0 + 8][kA + 8];
            }
#pragma unroll
            for (int j = 0; j < 4; j++) {
                int c0 = wn0 + j * 8 + g;
                bh[j][0] = *(const uint32_t*)&Bs_h[c0][kA];
                bh[j][1] = *(const uint32_t*)&Bs_h[c0][kA + 8];
                bl[j][0] = *(const uint32_t*)&Bs_l[c0][kA];
                bl[j][1] = *(const uint32_t*)&Bs_l[c0][kA + 8];
            }
#pragma unroll
            for (int i = 0; i < 2; i++)
#pragma unroll
                for (int j = 0; j < 4; j++) {
                    mma_bf16(acc[i][j], ah[i], bh[j]);
                    mma_bf16(acc[i][j], ah[i], bl[j]);
                    mma_bf16(acc[i][j], al[i], bh[j]);
                }
        }
        __syncthreads();
    }

#pragma unroll
    for (int i = 0; i < 2; i++)
#pragma unroll
        for (int j = 0; j < 4; j++) {
            int m_lo = m0 + wm0 + i * 16 + g;
            int col  = n0 + wn0 + j * 8 + tg * 2;
            if (m_lo < M) {
                float2 v = make_float2(acc[i][j][0], acc[i][j][1]);
                *(float2*)(C + (size_t)m_lo * 256 + col) = v;
            }
            if (m_lo + 8 < M) {
                float2 v = make_float2(acc[i][j][2], acc[i][j][3]);
                *(float2*)(C + (size_t)(m_lo + 8) * 256 + col) = v;
            }
        }
}

// ---------------- 2) per-(dst,type) incoming-edge histogram ---------------
__global__ void count_kernel(const int* __restrict__ dst,
                             const int* __restrict__ ef) {
    int i = blockIdx.x * blockDim.x + threadIdx.x;
    if (i < N_EDGES)
        atomicAdd(&g_cnt[(size_t)dst[i] * NUM_ET + ef[i]], 1);
}

// ---------------- 3) CSR offsets via warp-aggregated atomic ---------------
__global__ void offsets_kernel() {
    int n = blockIdx.x * blockDim.x + threadIdx.x;
    int lane = threadIdx.x & 31;
    int deg = 0;
    if (n < N_NODES) {
#pragma unroll
        for (int t = 0; t < NUM_ET; t++) deg += g_cnt[(size_t)n * NUM_ET + t];
    }
    int incl = deg;
#pragma unroll
    for (int o = 1; o < 32; o <<= 1) {
        int v = __shfl_up_sync(0xffffffffu, incl, o);
        if (lane >= o) incl += v;
    }
    int total = __shfl_sync(0xffffffffu, incl, 31);
    int base = 0;
    if (lane == 0) base = atomicAdd(&g_total, total);
    base = __shfl_sync(0xffffffffu, base, 0);
    if (n < N_NODES) {
        int off = base + incl - deg;
        g_off[n] = off;
        g_cur[n] = off;
        g_deg[n] = deg;
    }
}

// ---------------- 4) per-node softmax table w[n,t,h] ----------------------
__global__ void node_softmax_kernel(const float* __restrict__ emb) {
    int idx = blockIdx.x * blockDim.x + threadIdx.x;
    if (idx >= N_NODES * NUM_HEADS) return;
    int n = idx >> 3;
    int h = idx & 7;

    int c[NUM_ET];
    float ev[NUM_ET];
#pragma unroll
    for (int t = 0; t < NUM_ET; t++) {
        c[t] = g_cnt[(size_t)n * NUM_ET + t];
        ev[t] = emb[t * NUM_HEADS + h];
    }
    float m = -INFINITY;
#pragma unroll
    for (int t = 0; t < NUM_ET; t++)
        if (c[t] > 0) m = fmaxf(m, ev[t]);

    float ex[NUM_ET];
    float denom = 0.f;
#pragma unroll
    for (int t = 0; t < NUM_ET; t++) {
        ex[t] = expf(ev[t] - m);
        denom += (float)c[t] * ex[t];
    }
    float inv = 1.f / denom;  // denom==0 only for isolated nodes -> w unread
#pragma unroll
    for (int t = 0; t < NUM_ET; t++)
        g_w[((size_t)n * NUM_ET + t) * NUM_HEADS + h] = ex[t] * inv;
}

// ---------------- 5) scatter edges into CSR + write attn ------------------
__global__ void scatter_attn_kernel(const int* __restrict__ src,
                                    const int* __restrict__ dst,
                                    const int* __restrict__ ef,
                                    float* __restrict__ attn_out) {
    int e = blockIdx.x * blockDim.x + threadIdx.x;
    if (e >= N_EDGES) return;
    int s = src[e];
    int d = dst[e];
    int t = ef[e];
    int pos = atomicAdd(&g_cur[d], 1);
    g_csr[pos] = s | (t << 16);   // src < 65536, fits 16 bits

    const float4* w4 = (const float4*)(g_w + ((size_t)d * NUM_ET + t) * NUM_HEADS);
    float4 w0 = __ldg(w4);
    float4 w1 = __ldg(w4 + 1);
    float4* ao = (float4*)(attn_out + (size_t)e * NUM_HEADS);
    ao[0] = w0;
    ao[1] = w1;
}

// ---------------- 6) CSR aggregation: 1 warp per dst, no atomics ----------
__global__ __launch_bounds__(256) void agg_csr_kernel(float* __restrict__ rst) {
    __shared__ float sw[8][NUM_ET * NUM_HEADS];
    const int warp = threadIdx.x >> 5;
    const int lane = threadIdx.x & 31;
    const int d = blockIdx.x * 8 + warp;
    if (d >= N_NODES) return;

    // stage this node's 40 softmax weights in shared
    sw[warp][lane] = g_w[(size_t)d * 40 + lane];
    if (lane < 8) sw[warp][32 + lane] = g_w[(size_t)d * 40 + 32 + lane];
    __syncwarp();

    const int off = g_off[d];
    const int deg = g_deg[d];
    const int h0 = lane >> 3;

    float4 acc0 = make_float4(0.f, 0.f, 0.f, 0.f);
    float4 acc1 = make_float4(0.f, 0.f, 0.f, 0.f);

    int i = 0;
    for (; i + 2 <= deg; i += 2) {
        int p0 = g_csr[off + i];
        int p1 = g_csr[off + i + 1];
        int s0 = p0 & 0xFFFF, t0 = p0 >> 16;
        int s1 = p1 & 0xFFFF, t1 = p1 >> 16;
        const float4* f0 = (const float4*)(g_feat_src + (size_t)s0 * HD);
        const float4* f1 = (const float4*)(g_feat_src + (size_t)s1 * HD);
        float4 v00 = __ldg(f0 + lane), v01 = __ldg(f0 + lane + 32);
        float4 v10 = __ldg(f1 + lane), v11 = __ldg(f1 + lane + 32);
        float a00 = sw[warp][t0 * 8 + h0], a01 = sw[warp][t0 * 8 + h0 + 4];
        float a10 = sw[warp][t1 * 8 + h0], a11 = sw[warp][t1 * 8 + h0 + 4];
        acc0.x += a00 * v00.x; acc0.y += a00 * v00.y; acc0.z += a00 * v00.z; acc0.w += a00 * v00.w;
        acc1.x += a01 * v01.x; acc1.y += a01 * v01.y; acc1.z += a01 * v01.z; acc1.w += a01 * v01.w;
        acc0.x += a10 * v10.x; acc0.y += a10 * v10.y; acc0.z += a10 * v10.z; acc0.w += a10 * v10.w;
        acc1.x += a11 * v11.x; acc1.y += a11 * v11.y; acc1.z += a11 * v11.z; acc1.w += a11 * v11.w;
    }
    if (i < deg) {
        int p0 = g_csr[off + i];
        int s0 = p0 & 0xFFFF, t0 = p0 >> 16;
        const float4* f0 = (const float4*)(g_feat_src + (size_t)s0 * HD);
        float4 v00 = __ldg(f0 + lane), v01 = __ldg(f0 + lane + 32);
        float a00 = sw[warp][t0 * 8 + h0], a01 = sw[warp][t0 * 8 + h0 + 4];
        acc0.x += a00 * v00.x; acc0.y += a00 * v00.y; acc0.z += a00 * v00.z; acc0.w += a00 * v00.w;
        acc1.x += a01 * v01.x; acc1.y += a01 * v01.y; acc1.z += a01 * v01.z; acc1.w += a01 * v01.w;
    }

    float4* out = (float4*)(rst + (size_t)d * HD);
    out[lane]      = acc0;
    out[lane + 32] = acc1;
}

// ---------------- launch ---------------------------------------------------
extern "C" void kernel_launch(void* const* d_in, const int* in_sizes, int n_in,
                              void* d_out, int out_size) {
    const float* feat   = (const float*)d_in[0];   // [N, 256]
    const float* fc_w   = (const float*)d_in[1];   // [256, 256]
    const float* emb    = (const float*)d_in[2];   // [5, 8]
    const int*   e_feat = (const int*)d_in[3];     // [E]
    const int*   src    = (const int*)d_in[4];     // [E]
    const int*   dst    = (const int*)d_in[5];     // [E]

    float* out_rst  = (float*)d_out;                           // [N, 8, 32]
    float* out_attn = (float*)d_out + (size_t)N_NODES * HD;    // [E, 8]

    void* cnt_ptr = nullptr;
    void* fs_ptr  = nullptr;
    void* tot_ptr = nullptr;
    cudaGetSymbolAddress(&cnt_ptr, g_cnt);
    cudaGetSymbolAddress(&fs_ptr, g_feat_src);
    cudaGetSymbolAddress(&tot_ptr, g_total);

    cudaMemsetAsync(cnt_ptr, 0, (size_t)N_NODES * NUM_ET * sizeof(int));
    cudaMemsetAsync(tot_ptr, 0, sizeof(int));

    // 1) GEMM (tensor cores, split-bf16 x3)
    {
        dim3 grid((N_NODES + 127) / 128, HD / 64);
        gemm_bf16x3_kernel<<<grid, 256>>>(feat, fc_w, (float*)fs_ptr, N_NODES);
    }
    // 2) histogram
    count_kernel<<<(N_EDGES + 255) / 256, 256>>>(dst, e_feat);
    // 3) CSR offsets
    offsets_kernel<<<(N_NODES + 255) / 256, 256>>>();
    // 4) per-node softmax table
    node_softmax_kernel<<<(N_NODES * NUM_HEADS + 255) / 256, 256>>>(emb);
    // 5) scatter edges to CSR + attn output
    scatter_attn_kernel<<<(N_EDGES + 255) / 256, 256>>>(src, dst, e_feat, out_attn);
    // 6) aggregation (no atomics)
    agg_csr_kernel<<<(N_NODES + 7) / 8, 256>>>(out_rst);
}

// round 3
// speedup vs baseline: 2.0829x; 1.0785x over previous
#include <cuda_runtime.h>
#include <cuda_bf16.h>
#include <cuda_fp16.h>
#include <math.h>
#include <stddef.h>
#include <stdint.h>

#define N_NODES 50000
#define N_EDGES 800000
#define IN_FEATS 256
#define HD 256          // NUM_HEADS * OUT_FEATS
#define NUM_HEADS 8
#define OUT_FEATS 32
#define NUM_ET 5
#define PADK 264        // padded k-row length for GEMM smem

// ---------------- scratch (static device globals; no allocation) ----------
__device__ __half g_feat_src[(size_t)N_NODES * HD];         // 25.6 MB (fp16)
__device__ int    g_cnt[(size_t)N_NODES * NUM_ET];          // 1 MB
__device__ float  g_w[(size_t)N_NODES * NUM_ET * NUM_HEADS];// 8 MB
__device__ int    g_off[N_NODES];
__device__ int    g_deg[N_NODES];
__device__ int    g_cur[N_NODES];
__device__ int    g_csr[N_EDGES];
__device__ int    g_total;

// =====================================================================
// 1) GEMM: C[M,256](fp16) = A[M,256] * B[256,256]^T, split-bf16 x3 MMA.
//    A tile (BM=128, full K) split hi/lo into smem ONCE per block,
//    then loop n0 over 4 x 64-col B tiles. 512 threads, 16 warps (4Mx4N),
//    warp tile 32x16. Fragments via ldmatrix.x4.
// =====================================================================
__device__ __forceinline__ void mma_bf16(float* c, const uint32_t* a,
                                         uint32_t b0, uint32_t b1) {
    asm volatile(
        "mma.sync.aligned.m16n8k16.row.col.f32.bf16.bf16.f32 "
        "{%0,%1,%2,%3},{%4,%5,%6,%7},{%8,%9},{%0,%1,%2,%3};\n"
        : "+f"(c[0]), "+f"(c[1]), "+f"(c[2]), "+f"(c[3])
        : "r"(a[0]), "r"(a[1]), "r"(a[2]), "r"(a[3]), "r"(b0), "r"(b1));
}

__device__ __forceinline__ void ldmx4(uint32_t* r, const __nv_bfloat16* p) {
    uint32_t addr = (uint32_t)__cvta_generic_to_shared(p);
    asm volatile("ldmatrix.sync.aligned.m8n8.x4.shared.b16 {%0,%1,%2,%3},[%4];"
                 : "=r"(r[0]), "=r"(r[1]), "=r"(r[2]), "=r"(r[3]) : "r"(addr));
}

__device__ __forceinline__ void split_store(__nv_bfloat16* ph, __nv_bfloat16* pl, float4 v) {
    __nv_bfloat162 h01, h23, l01, l23;
    h01.x = __float2bfloat16(v.x);
    h01.y = __float2bfloat16(v.y);
    h23.x = __float2bfloat16(v.z);
    h23.y = __float2bfloat16(v.w);
    l01.x = __float2bfloat16(v.x - __bfloat162float(h01.x));
    l01.y = __float2bfloat16(v.y - __bfloat162float(h01.y));
    l23.x = __float2bfloat16(v.z - __bfloat162float(h23.x));
    l23.y = __float2bfloat16(v.w - __bfloat162float(h23.y));
    *(__nv_bfloat162*)(ph)     = h01;
    *(__nv_bfloat162*)(ph + 2) = h23;
    *(__nv_bfloat162*)(pl)     = l01;
    *(__nv_bfloat162*)(pl + 2) = l23;
}

#define GEMM_SMEM_BYTES ((128 * 2 + 64 * 2) * PADK * 2)   // 202752

__global__ __launch_bounds__(512) void gemm_bf16x3_kernel(
    const float* __restrict__ A, const float* __restrict__ B,
    __half* __restrict__ C, int M) {
    extern __shared__ char smem_raw[];
    __nv_bfloat16* As_h = (__nv_bfloat16*)smem_raw;
    __nv_bfloat16* As_l = As_h + 128 * PADK;
    __nv_bfloat16* Bs_h = As_l + 128 * PADK;
    __nv_bfloat16* Bs_l = Bs_h + 64 * PADK;

    const int tid = threadIdx.x;
    const int m0 = blockIdx.x * 128;
    const int warp = tid >> 5, lane = tid & 31;
    const int wm = (warp >> 2) * 32;       // warp m origin (4 groups)
    const int wn = (warp & 3) * 16;        // warp n origin within 64-tile
    const int g = lane >> 2, tg = lane & 3;
    // ldmatrix per-lane address offsets
    const int lm_row = (lane & 7) + ((lane >> 3) & 1) * 8;
    const int lm_col = (lane >> 4) * 8;

    // ---- load + split full A tile: 128 x 256 ----
#pragma unroll
    for (int r = 0; r < 16; r++) {
        int idx = tid + r * 512;
        int row = idx >> 6, c4 = (idx & 63) * 4;
        float4 v = make_float4(0.f, 0.f, 0.f, 0.f);
        if (m0 + row < M)
            v = __ldg((const float4*)(A + (size_t)(m0 + row) * 256 + c4));
        split_store(&As_h[row * PADK + c4], &As_l[row * PADK + c4], v);
    }

    for (int n0 = 0; n0 < 256; n0 += 64) {
        __syncthreads();   // protect Bs from previous iteration's readers
        // ---- load + split B tile: 64 x 256 ----
#pragma unroll
        for (int r = 0; r < 8; r++) {
            int idx = tid + r * 512;
            int row = idx >> 6, c4 = (idx & 63) * 4;
            float4 v = __ldg((const float4*)(B + (size_t)(n0 + row) * 256 + c4));
            split_store(&Bs_h[row * PADK + c4], &Bs_l[row * PADK + c4], v);
        }
        __syncthreads();

        float acc[2][2][4];
#pragma unroll
        for (int i = 0; i < 2; i++)
#pragma unroll
            for (int j = 0; j < 2; j++)
#pragma unroll
                for (int q = 0; q < 4; q++) acc[i][j][q] = 0.f;

#pragma unroll
        for (int kf = 0; kf < 16; kf++) {
            const int kb = kf * 16;
            uint32_t ah[2][4], al[2][4], bH[4], bL[4];
#pragma unroll
            for (int i = 0; i < 2; i++) {
                const int arow = (wm + i * 16 + lm_row) * PADK + kb + lm_col;
                ldmx4(ah[i], As_h + arow);
                ldmx4(al[i], As_l + arow);
            }
            {
                const int brow = (wn + lm_row) * PADK + kb + lm_col;
                ldmx4(bH, Bs_h + brow);
                ldmx4(bL, Bs_l + brow);
            }
#pragma unroll
            for (int i = 0; i < 2; i++)
#pragma unroll
                for (int j = 0; j < 2; j++) {
                    mma_bf16(acc[i][j], ah[i], bH[j], bH[j + 2]);
                    mma_bf16(acc[i][j], ah[i], bL[j], bL[j + 2]);
                    mma_bf16(acc[i][j], al[i], bH[j], bH[j + 2]);
                }
        }

        // ---- epilogue: fp16 store ----
#pragma unroll
        for (int i = 0; i < 2; i++)
#pragma unroll
            for (int j = 0; j < 2; j++) {
                int m_lo = m0 + wm + i * 16 + g;
                int col  = n0 + wn + j * 8 + tg * 2;
                if (m_lo < M)
                    *(__half2*)(C + (size_t)m_lo * 256 + col) =
                        __floats2half2_rn(acc[i][j][0], acc[i][j][1]);
                if (m_lo + 8 < M)
                    *(__half2*)(C + (size_t)(m_lo + 8) * 256 + col) =
                        __floats2half2_rn(acc[i][j][2], acc[i][j][3]);
            }
    }
}

// ---------------- 2) per-(dst,type) histogram (+ clear g_total) -----------
__global__ void count_kernel(const int* __restrict__ dst,
                             const int* __restrict__ ef) {
    int i = blockIdx.x * blockDim.x + threadIdx.x;
    if (i == 0) g_total = 0;
    if (i < N_EDGES)
        atomicAdd(&g_cnt[(size_t)dst[i] * NUM_ET + ef[i]], 1);
}

// ---------------- 3) fused CSR offsets + per-node softmax table -----------
__global__ void offsets_softmax_kernel(const float* __restrict__ emb) {
    int n = blockIdx.x * blockDim.x + threadIdx.x;
    int lane = threadIdx.x & 31;

    int c[NUM_ET];
    int deg = 0;
    if (n < N_NODES) {
#pragma unroll
        for (int t = 0; t < NUM_ET; t++) {
            c[t] = g_cnt[(size_t)n * NUM_ET + t];
            deg += c[t];
        }
    }
    // warp-aggregated exclusive scan for CSR offsets
    int incl = deg;
#pragma unroll
    for (int o = 1; o < 32; o <<= 1) {
        int v = __shfl_up_sync(0xffffffffu, incl, o);
        if (lane >= o) incl += v;
    }
    int total = __shfl_sync(0xffffffffu, incl, 31);
    int base = 0;
    if (lane == 0) base = atomicAdd(&g_total, total);
    base = __shfl_sync(0xffffffffu, base, 0);

    if (n < N_NODES) {
        int off = base + incl - deg;
        g_off[n] = off;
        g_cur[n] = off;
        g_deg[n] = deg;

#pragma unroll
        for (int h = 0; h < NUM_HEADS; h++) {
            float ev[NUM_ET];
            float m = -INFINITY;
#pragma unroll
            for (int t = 0; t < NUM_ET; t++) {
                ev[t] = __ldg(emb + t * NUM_HEADS + h);
                if (c[t] > 0) m = fmaxf(m, ev[t]);
            }
            float ex[NUM_ET];
            float denom = 0.f;
#pragma unroll
            for (int t = 0; t < NUM_ET; t++) {
                ex[t] = expf(ev[t] - m);
                denom += (float)c[t] * ex[t];
            }
            float inv = 1.f / denom;   // NaN only for deg==0 nodes (unread)
#pragma unroll
            for (int t = 0; t < NUM_ET; t++)
                g_w[((size_t)n * NUM_ET + t) * NUM_HEADS + h] = ex[t] * inv;
        }
    }
}

// ---------------- 4) scatter edges into CSR + write attn ------------------
__global__ void scatter_attn_kernel(const int* __restrict__ src,
                                    const int* __restrict__ dst,
                                    const int* __restrict__ ef,
                                    float* __restrict__ attn_out) {
    int e = blockIdx.x * blockDim.x + threadIdx.x;
    if (e >= N_EDGES) return;
    int s = src[e];
    int d = dst[e];
    int t = ef[e];
    int pos = atomicAdd(&g_cur[d], 1);
    g_csr[pos] = s | (t << 16);   // src < 65536 fits 16 bits

    const float4* w4 = (const float4*)(g_w + ((size_t)d * NUM_ET + t) * NUM_HEADS);
    float4 w0 = __ldg(w4);
    float4 w1 = __ldg(w4 + 1);
    float4* ao = (float4*)(attn_out + (size_t)e * NUM_HEADS);
    ao[0] = w0;
    ao[1] = w1;
}

// ---------------- 5) CSR aggregation: 1 warp/dst, fp16 gather -------------
__global__ __launch_bounds__(256) void agg_csr_kernel(float* __restrict__ rst) {
    __shared__ float sw[8][NUM_ET * NUM_HEADS];
    const int warp = threadIdx.x >> 5;
    const int lane = threadIdx.x & 31;
    const int d = blockIdx.x * 8 + warp;
    if (d >= N_NODES) return;

    sw[warp][lane] = g_w[(size_t)d * 40 + lane];
    if (lane < 8) sw[warp][32 + lane] = g_w[(size_t)d * 40 + 32 + lane];
    __syncwarp();

    const int off = g_off[d];
    const int deg = g_deg[d];
    const int h0 = lane >> 2;                     // head of this lane's 8 cols
    const uint4* base = (const uint4*)g_feat_src; // row = 32 uint4 (256 fp16)

    float acc[8];
#pragma unroll
    for (int q = 0; q < 8; q++) acc[q] = 0.f;

    int i = 0;
    for (; i + 4 <= deg; i += 4) {
        int p0 = g_csr[off + i];
        int p1 = g_csr[off + i + 1];
        int p2 = g_csr[off + i + 2];
        int p3 = g_csr[off + i + 3];
        uint4 v0 = __ldg(base + (size_t)(p0 & 0xFFFF) * 32 + lane);
        uint4 v1 = __ldg(base + (size_t)(p1 & 0xFFFF) * 32 + lane);
        uint4 v2 = __ldg(base + (size_t)(p2 & 0xFFFF) * 32 + lane);
        uint4 v3 = __ldg(base + (size_t)(p3 & 0xFFFF) * 32 + lane);
        float w0 = sw[warp][(p0 >> 16) * 8 + h0];
        float w1 = sw[warp][(p1 >> 16) * 8 + h0];
        float w2 = sw[warp][(p2 >> 16) * 8 + h0];
        float w3 = sw[warp][(p3 >> 16) * 8 + h0];
        const uint32_t* u0 = &v0.x;
        const uint32_t* u1 = &v1.x;
        const uint32_t* u2 = &v2.x;
        const uint32_t* u3 = &v3.x;
#pragma unroll
        for (int q = 0; q < 4; q++) {
            float2 f0 = __half22float2(*(const __half2*)&u0[q]);
            float2 f1 = __half22float2(*(const __half2*)&u1[q]);
            float2 f2 = __half22float2(*(const __half2*)&u2[q]);
            float2 f3 = __half22float2(*(const __half2*)&u3[q]);
            acc[q * 2]     += w0 * f0.x + w1 * f1.x + w2 * f2.x + w3 * f3.x;
            acc[q * 2 + 1] += w0 * f0.y + w1 * f1.y + w2 * f2.y + w3 * f3.y;
        }
    }
    for (; i < deg; i++) {
        int p0 = g_csr[off + i];
        uint4 v0 = __ldg(base + (size_t)(p0 & 0xFFFF) * 32 + lane);
        float w0 = sw[warp][(p0 >> 16) * 8 + h0];
        const uint32_t* u0 = &v0.x;
#pragma unroll
        for (int q = 0; q < 4; q++) {
            float2 f0 = __half22float2(*(const __half2*)&u0[q]);
            acc[q * 2]     += w0 * f0.x;
            acc[q * 2 + 1] += w0 * f0.y;
        }
    }

    // write: lane covers cols [lane*8, lane*8+8) of rst row d
    float4* out = (float4*)(rst + (size_t)d * HD) + lane * 2;
    out[0] = make_float4(acc[0], acc[1], acc[2], acc[3]);
    out[1] = make_float4(acc[4], acc[5], acc[6], acc[7]);
}

// ---------------- launch ---------------------------------------------------
extern "C" void kernel_launch(void* const* d_in, const int* in_sizes, int n_in,
                              void* d_out, int out_size) {
    const float* feat   = (const float*)d_in[0];   // [N, 256]
    const float* fc_w   = (const float*)d_in[1];   // [256, 256]
    const float* emb    = (const float*)d_in[2];   // [5, 8]
    const int*   e_feat = (const int*)d_in[3];     // [E]
    const int*   src    = (const int*)d_in[4];     // [E]
    const int*   dst    = (const int*)d_in[5];     // [E]

    float* out_rst  = (float*)d_out;                           // [N, 8, 32]
    float* out_attn = (float*)d_out + (size_t)N_NODES * HD;    // [E, 8]

    void* cnt_ptr = nullptr;
    void* fs_ptr  = nullptr;
    cudaGetSymbolAddress(&cnt_ptr, g_cnt);
    cudaGetSymbolAddress(&fs_ptr, g_feat_src);

    cudaMemsetAsync(cnt_ptr, 0, (size_t)N_NODES * NUM_ET * sizeof(int));

    // 1) GEMM (tensor cores, split-bf16 x3, fp16 output)
    cudaFuncSetAttribute(gemm_bf16x3_kernel,
                         cudaFuncAttributeMaxDynamicSharedMemorySize,
                         GEMM_SMEM_BYTES);
    gemm_bf16x3_kernel<<<(N_NODES + 127) / 128, 512, GEMM_SMEM_BYTES>>>(
        feat, fc_w, (__half*)fs_ptr, N_NODES);
    // 2) histogram (+ clears g_total)
    count_kernel<<<(N_EDGES + 255) / 256, 256>>>(dst, e_feat);
    // 3) fused offsets + softmax
    offsets_softmax_kernel<<<(N_NODES + 255) / 256, 256>>>(emb);
    // 4) scatter edges to CSR + attn output
    scatter_attn_kernel<<<(N_EDGES + 255) / 256, 256>>>(src, dst, e_feat, out_attn);
    // 5) aggregation (no atomics, fp16 gather)  — launch #5 for ncu
    agg_csr_kernel<<<(N_NODES + 7) / 8, 256>>>(out_rst);
}